// round 14
// baseline (speedup 1.0000x reference)
#include <cuda_runtime.h>
#include <math.h>

#define NV 50000
#define NE 25000
#define NNZ 200000
#define FIN 128
#define NHID 256
#define ND 4
#define NH1 16
#define NC 40

// ---------------- device scratch (static; no allocation) ----------------
// Only ever referenced inside device code (GB300 ATS makes host-shadow
// dereference silently read zeros — never pass these as kernel args).
__device__ float g_u1[FIN * 4];
__device__ float g_u2[FIN * 4];
__device__ float g_WA[FIN * 64];
__device__ float g_bbG[64];
__device__ float g_ba1[4];
__device__ float g_ba2[4];

__device__ float4 g_a1[NV];
__device__ float4 g_a2[NE];

__device__ int g_cnt_e[NE], g_cnt_v[NV];
__device__ int g_off_e[NE], g_off_v[NV];
__device__ int g_cur_e[NE], g_cur_v[NV];
__device__ float g_inv_e[NE], g_inv_v[NV];

#define NBE 25
#define NBV 49
__device__ int g_aggE[NBE];    // published block aggregates (+1 ready-flag)
__device__ int g_aggV[NBV];

__device__ int g_vid_e[NNZ];   // node id per edge-CSR slot
__device__ int g_eid_v[NNZ];   // edge id per node-CSR slot
__device__ float4 g_se[NNZ];   // s in edge-CSR order
__device__ float4 g_sv[NNZ];   // s in node-CSR order

__device__ float g_P0[NV * 64];
__device__ float g_m[NE * 64];
__device__ float g_H1[NV * 64];
__device__ float g_T[NV * 64];

// ================= init: zero counters/flags + weight folding =================
#define ZBLK 196     // ceil(50000/256)
__global__ __launch_bounds__(256) void init_all(
    const float* __restrict__ Wlin, const float* __restrict__ blin,
    const float* __restrict__ w1, const float* __restrict__ w2,
    const float* __restrict__ W0) {
    int b = blockIdx.x, t = threadIdx.x;
    if (b < ZBLK) {
        int i = b * 256 + t;
        if (i < NE) { g_cnt_e[i] = 0; g_cur_e[i] = 0; }
        if (i < NV) { g_cnt_v[i] = 0; g_cur_v[i] = 0; }
        if (b == 0) {
            if (t < NBE) g_aggE[t] = 0;
            else if (t < NBE + NBV) g_aggV[t - NBE] = 0;
        }
        return;
    }
    int pb = b - ZBLK;                 // 0..128
    if (pb < FIN) {
        int f = pb;
        if (t < 64) {
            int d = t >> 4, c = t & 15;
            const float* wl = Wlin + f * (ND * NHID) + d * NHID;
            float acc = 0.0f;
            #pragma unroll 8
            for (int h = 0; h < NHID; h++) acc += wl[h] * W0[h * NH1 + c];
            g_WA[f * 64 + t] = acc;
        } else if (t < 68) {
            int d = t - 64;
            const float* wl = Wlin + f * (ND * NHID) + d * NHID;
            float acc = 0.0f;
            #pragma unroll 8
            for (int h = 0; h < NHID; h++) acc += wl[h] * w1[h * ND + d];
            g_u1[f * 4 + d] = acc;
        } else if (t < 72) {
            int d = t - 68;
            const float* wl = Wlin + f * (ND * NHID) + d * NHID;
            float acc = 0.0f;
            #pragma unroll 8
            for (int h = 0; h < NHID; h++) acc += wl[h] * w2[h * ND + d];
            g_u2[f * 4 + d] = acc;
        }
    } else {
        if (t < 64) {
            int d = t >> 4, c = t & 15;
            const float* bl = blin + d * NHID;
            float acc = 0.0f;
            #pragma unroll 8
            for (int h = 0; h < NHID; h++) acc += bl[h] * W0[h * NH1 + c];
            g_bbG[t] = acc;
        } else if (t < 68) {
            int d = t - 64;
            const float* bl = blin + d * NHID;
            float acc = 0.0f;
            for (int h = 0; h < NHID; h++) acc += bl[h] * w1[h * ND + d];
            g_ba1[d] = acc;
        } else if (t < 72) {
            int d = t - 68;
            const float* bl = blin + d * NHID;
            float acc = 0.0f;
            for (int h = 0; h < NHID; h++) acc += bl[h] * w2[h * ND + d];
            g_ba2[d] = acc;
        }
    }
}

// ================= structural kernels =================
__global__ void count_deg(const int* __restrict__ node_idx,
                          const int* __restrict__ edge_idx) {
    int i = blockIdx.x * blockDim.x + threadIdx.x;
    if (i >= NNZ) return;
    atomicAdd(&g_cnt_e[edge_idx[i]], 1);
    atomicAdd(&g_cnt_v[node_idx[i]], 1);
}

// single-pass scan with decoupled block aggregates (all 74 blocks co-resident)
__device__ __forceinline__ void scan_onepass_dev(const int* __restrict__ in, int n,
                                                 int* __restrict__ out,
                                                 float* __restrict__ inv,
                                                 int* __restrict__ agg,
                                                 int nblk, int blk) {
    __shared__ int wsum[32];
    __shared__ int s_pfx;
    int t = threadIdx.x;
    int i = blk * 1024 + t;
    int v = (i < n) ? in[i] : 0;
    if (i < n) inv[i] = v > 0 ? 1.0f / (float)v : 0.0f;
    int lane = t & 31, wid = t >> 5;
    int xv = v;
    #pragma unroll
    for (int o = 1; o < 32; o <<= 1) {
        int y = __shfl_up_sync(0xFFFFFFFFu, xv, o);
        if (lane >= o) xv += y;
    }
    if (lane == 31) wsum[wid] = xv;
    __syncthreads();
    if (wid == 0) {
        int s = wsum[lane];
        #pragma unroll
        for (int o = 1; o < 32; o <<= 1) {
            int y = __shfl_up_sync(0xFFFFFFFFu, s, o);
            if (lane >= o) s += y;
        }
        wsum[lane] = s;
        if (lane == 31) atomicExch(&agg[blk], s + 1);   // publish total (+1 flag)
        int sum = 0;
        for (int j = lane; j < blk; j += 32) {
            int a;
            do { a = atomicAdd(&agg[j], 0); } while (a == 0);
            sum += a - 1;
        }
        #pragma unroll
        for (int o = 16; o; o >>= 1) sum += __shfl_down_sync(0xFFFFFFFFu, sum, o);
        if (lane == 0) s_pfx = sum;
    }
    __syncthreads();
    int base = (wid > 0 ? wsum[wid - 1] : 0) + s_pfx;
    if (i < n) out[i] = base + xv - v;
}

__global__ void scan_all() {
    if (blockIdx.x < NBE)
        scan_onepass_dev(g_cnt_e, NE, g_off_e, g_inv_e, g_aggE, NBE, blockIdx.x);
    else
        scan_onepass_dev(g_cnt_v, NV, g_off_v, g_inv_v, g_aggV, NBV, blockIdx.x - NBE);
}

// ================= fused GEMMs: node (P0, a1) + edge (a2) =================
// node tile: 64 rows x 64 cols, 128 thr, 8x4 regs/thread -> 10.7 FMA per LDS.128
// edge: ONE thread per edge, float4 row loads, u2 broadcast from smem
#define NODE_BLOCKS 782      // ceil(NV/64)
#define EDGE_BLOCKS 196      // ceil(NE/128)
__global__ __launch_bounds__(128) void gemms_kernel(const float* __restrict__ x,
                                                    const float* __restrict__ eattr) {
    if (blockIdx.x < NODE_BLOCKS) {
        __shared__ __align__(16) float shX[64][68];
        __shared__ __align__(16) float shWT[64][68];
        __shared__ __align__(16) float shUT[4][132];
        int t = threadIdx.x;
        int tx = t & 15, ty = t >> 4;          // tx 0..15, ty 0..7
        int row0 = blockIdx.x * 64;
        for (int i = t; i < 512; i += 128) {
            int d = i >> 7, f = i & 127;
            shUT[d][f] = g_u1[f * 4 + d];
        }
        float acc[8][4] = {};
        float accA0 = 0.0f, accA1 = 0.0f;
        int rA = t >> 2, dA = t & 3;           // rA 0..31; rows rA and rA+32
        for (int ch = 0; ch < 2; ch++) {
            int f0 = ch * 64;
            __syncthreads();
            for (int i = t; i < 4096; i += 128) {
                int r = i >> 6, f = i & 63;
                int v = row0 + r;
                shX[r][f] = (v < NV) ? x[v * FIN + f0 + f] : 0.0f;
            }
            for (int i = t; i < 4096; i += 128) {
                int f = i >> 6, c = i & 63;
                shWT[c][f] = g_WA[(f0 + f) * 64 + c];
            }
            __syncthreads();
            #pragma unroll
            for (int f4 = 0; f4 < 16; f4++) {
                float4 wv[4];
                #pragma unroll
                for (int q = 0; q < 4; q++)
                    wv[q] = *(const float4*)&shWT[tx + 16 * q][f4 * 4];
                #pragma unroll
                for (int a = 0; a < 8; a++) {
                    float4 xr = *(const float4*)&shX[ty + 8 * a][f4 * 4];
                    #pragma unroll
                    for (int q = 0; q < 4; q++)
                        acc[a][q] += xr.x * wv[q].x + xr.y * wv[q].y
                                   + xr.z * wv[q].z + xr.w * wv[q].w;
                }
            }
            #pragma unroll
            for (int f4 = 0; f4 < 16; f4++) {
                float4 uv = *(const float4*)&shUT[dA][f0 + f4 * 4];
                float4 x0 = *(const float4*)&shX[rA][f4 * 4];
                float4 x1 = *(const float4*)&shX[rA + 32][f4 * 4];
                accA0 += x0.x * uv.x + x0.y * uv.y + x0.z * uv.z + x0.w * uv.w;
                accA1 += x1.x * uv.x + x1.y * uv.y + x1.z * uv.z + x1.w * uv.w;
            }
        }
        #pragma unroll
        for (int a = 0; a < 8; a++) {
            int v = row0 + ty + 8 * a;
            if (v >= NV) continue;
            #pragma unroll
            for (int q = 0; q < 4; q++) {
                int c = tx + 16 * q;
                g_P0[v * 64 + c] = acc[a][q] + g_bbG[c];
            }
        }
        int vA0 = row0 + rA;
        int vA1 = row0 + rA + 32;
        if (vA0 < NV) ((float*)g_a1)[vA0 * 4 + dA] = accA0 + g_ba1[dA];
        if (vA1 < NV) ((float*)g_a1)[vA1 * 4 + dA] = accA1 + g_ba1[dA];
    } else {
        // one thread per edge: a2[e][0..3] = eattr[e] . u2[:, 0..3] + ba2
        __shared__ __align__(16) float shU2[4][132];
        int t = threadIdx.x;
        for (int i = t; i < 512; i += 128) {
            int d = i >> 7, f = i & 127;
            shU2[d][f] = g_u2[f * 4 + d];
        }
        __syncthreads();
        int e = (blockIdx.x - NODE_BLOCKS) * 128 + t;
        if (e >= NE) return;
        const float4* row = (const float4*)(eattr + e * FIN);
        float a0 = g_ba2[0], a1 = g_ba2[1], a2 = g_ba2[2], a3 = g_ba2[3];
        #pragma unroll 8
        for (int i = 0; i < 32; i++) {
            float4 xv = row[i];
            float4 u0 = *(const float4*)&shU2[0][i * 4];
            float4 u1v = *(const float4*)&shU2[1][i * 4];
            float4 u2v = *(const float4*)&shU2[2][i * 4];
            float4 u3 = *(const float4*)&shU2[3][i * 4];
            a0 += xv.x * u0.x + xv.y * u0.y + xv.z * u0.z + xv.w * u0.w;
            a1 += xv.x * u1v.x + xv.y * u1v.y + xv.z * u1v.z + xv.w * u1v.w;
            a2 += xv.x * u2v.x + xv.y * u2v.y + xv.z * u2v.z + xv.w * u2v.w;
            a3 += xv.x * u3.x + xv.y * u3.y + xv.z * u3.z + xv.w * u3.w;
        }
        g_a2[e] = make_float4(a0, a1, a2, a3);
    }
}

// ================= fill CSR + sheaf scalars (fused; a1/a2 must be ready) ======
__global__ void fill_csr_s(const int* __restrict__ node_idx,
                           const int* __restrict__ edge_idx,
                           const float* __restrict__ bs) {
    int i = blockIdx.x * blockDim.x + threadIdx.x;
    if (i >= NNZ) return;
    int e = edge_idx[i];
    int v = node_idx[i];
    float4 A = g_a1[v];
    float4 B = g_a2[e];
    float4 r;
    r.x = tanhf(A.x + B.x + bs[0]);
    r.y = tanhf(A.y + B.y + bs[1]);
    r.z = tanhf(A.z + B.z + bs[2]);
    r.w = tanhf(A.w + B.w + bs[3]);
    int p = atomicAdd(&g_cur_e[e], 1);
    int pos = g_off_e[e] + p;
    g_vid_e[pos] = v;
    g_se[pos] = r;
    int q = atomicAdd(&g_cur_v[v], 1);
    int pos2 = g_off_v[v] + q;
    g_eid_v[pos2] = e;
    g_sv[pos2] = r;
}

// ================= aggregation (warp/segment, payload CSR, float2) ===========
__device__ __forceinline__ float pick_s(const float4& s4, int dsel) {
    float lo = dsel < 1 ? s4.x : s4.y;
    float hi = dsel < 3 ? s4.z : s4.w;
    return dsel < 2 ? lo : hi;
}

__global__ void edge_agg(int src) {
    int w = (blockIdx.x * blockDim.x + threadIdx.x) >> 5;
    int lane = threadIdx.x & 31;
    if (w >= NE) return;
    const float* __restrict__ X = src ? g_H1 : g_P0;
    int beg = g_off_e[w], cnt = g_cnt_e[w];
    int dsel = lane >> 3;
    float2 acc = make_float2(0.0f, 0.0f);
    #pragma unroll 2
    for (int k = 0; k < cnt; k++) {
        int pos = beg + k;
        int v = g_vid_e[pos];
        float4 s4 = g_se[pos];
        float sd = pick_s(s4, dsel);
        float2 xr = *(const float2*)&X[v * 64 + lane * 2];
        acc.x += sd * xr.x;
        acc.y += sd * xr.y;
    }
    float inv = g_inv_e[w];
    ((float2*)g_m)[w * 32 + lane] = make_float2(acc.x * inv, acc.y * inv);
}

__global__ void node_agg(int layer, const float* __restrict__ b0) {
    int w = (blockIdx.x * blockDim.x + threadIdx.x) >> 5;
    int lane = threadIdx.x & 31;
    if (w >= NV) return;
    const float* __restrict__ Base = layer ? g_H1 : g_P0;
    float* __restrict__ Out = layer ? g_T : g_H1;
    int beg = g_off_v[w], cnt = g_cnt_v[w];
    int dsel = lane >> 3;
    float2 acc = make_float2(0.0f, 0.0f);
    #pragma unroll 2
    for (int k = 0; k < cnt; k++) {
        int pos = beg + k;
        int e = g_eid_v[pos];
        float4 s4 = g_sv[pos];
        float sd = pick_s(s4, dsel);
        float2 mr = ((const float2*)g_m)[e * 32 + lane];
        acc.x += sd * mr.x;
        acc.y += sd * mr.y;
    }
    float inv = g_inv_v[w];
    float2 base = ((const float2*)Base)[w * 32 + lane];
    float o0 = base.x - acc.x * inv;
    float o1 = base.y - acc.y * inv;
    if (layer == 0) {
        int c0 = lane * 2;
        o0 = fmaxf(o0 + b0[c0 & 15], 0.0f);
        o1 = fmaxf(o1 + b0[(c0 + 1) & 15], 0.0f);
    }
    ((float2*)Out)[w * 32 + lane] = make_float2(o0, o1);
}

// ================= final fused: out = relu(T @ blockdiag(W1) + b1) @ W2 ======
// shW1T [j][k] stride 20 -> phase B fully float4 (ratio 10.7)
#define FK2_FLOATS (800 + 40 + 40 * 172 + 64 * 68 + 64 * 164)
__global__ __launch_bounds__(320, 2)
void final_kernel(const float* __restrict__ W1, const float* __restrict__ b1,
                  const float* __restrict__ W2, float* __restrict__ out) {
    extern __shared__ float sh[];
    float* shW1T = sh;                 // [j][k] 40 x 20 = 800
    float* shb1  = sh + 800;           // 40
    float* shW2T = sh + 840;           // [j][k] stride 172 -> 6880
    float* shT   = sh + 7720;          // [r][c] stride 68 -> 4352
    float* shZ   = sh + 12072;         // [r][k] stride 164 (reused for partials)
    int t = threadIdx.x;
    for (int i = t; i < 640; i += 320) {
        int k = i / 40, j = i % 40;
        shW1T[j * 20 + k] = W1[i];
    }
    for (int i = t; i < 40; i += 320) shb1[i] = b1[i];
    for (int i = t; i < 6400; i += 320) {
        int k = i / 40, j = i % 40;
        shW2T[j * 172 + k] = W2[i];
    }
    int row0 = blockIdx.x * 64;
    for (int i = t; i < 4096; i += 320) {
        int r = i >> 6, c = i & 63;
        int v = row0 + r;
        shT[r * 68 + c] = (v < NV) ? g_T[v * 64 + c] : 0.0f;
    }
    __syncthreads();
    // Phase B: Z = relu(T @ blockdiag(W1) + b1); k vectorized by 4
    {
        int tx = t % 40, ty = t / 40;
        int d = tx / 10, cl = tx % 10;
        float zacc[8][4] = {};
        #pragma unroll
        for (int k4 = 0; k4 < 4; k4++) {
            int k = k4 * 4;
            float4 wv[4];
            #pragma unroll
            for (int q = 0; q < 4; q++)
                wv[q] = *(const float4*)&shW1T[(cl + 10 * q) * 20 + k];
            #pragma unroll
            for (int a = 0; a < 8; a++) {
                float4 tv = *(const float4*)&shT[(ty + 8 * a) * 68 + d * 16 + k];
                #pragma unroll
                for (int q = 0; q < 4; q++)
                    zacc[a][q] += tv.x * wv[q].x + tv.y * wv[q].y
                                + tv.z * wv[q].z + tv.w * wv[q].w;
            }
        }
        #pragma unroll
        for (int a = 0; a < 8; a++)
            #pragma unroll
            for (int q = 0; q < 4; q++) {
                int j = cl + 10 * q;
                shZ[(ty + 8 * a) * 164 + d * 40 + j] = fmaxf(zacc[a][q] + shb1[j], 0.0f);
            }
    }
    __syncthreads();
    // Phase C: out = Z @ W2. 80 tiles (8 rows x 4 cols) x 4-way split-K.
    {
        int g = t % 80, kh = t / 80;        // kh 0..3
        int rg = g % 8, cg = g / 8;         // rg 0..7, cg 0..9
        int j0 = cg * 4;
        float oa[8][4] = {};
        int kbeg = kh * 40;
        #pragma unroll
        for (int k4 = 0; k4 < 10; k4++) {
            int k = kbeg + k4 * 4;
            float4 zv[8], wv[4];
            #pragma unroll
            for (int a = 0; a < 8; a++) zv[a] = *(const float4*)&shZ[(rg + 8 * a) * 164 + k];
            #pragma unroll
            for (int q = 0; q < 4; q++) wv[q] = *(const float4*)&shW2T[(j0 + q) * 172 + k];
            #pragma unroll
            for (int a = 0; a < 8; a++)
                #pragma unroll
                for (int q = 0; q < 4; q++)
                    oa[a][q] += zv[a].x * wv[q].x + zv[a].y * wv[q].y
                              + zv[a].z * wv[q].z + zv[a].w * wv[q].w;
        }
        __syncthreads();                    // all shZ reads done
        float* shP = shZ;                   // reuse as partial staging (3 x 80 x 33)
        if (kh) {
            int base = (kh - 1) * 2656 + g * 33;
            #pragma unroll
            for (int a = 0; a < 8; a++)
                #pragma unroll
                for (int q = 0; q < 4; q++) shP[base + a * 4 + q] = oa[a][q];
        }
        __syncthreads();
        if (kh == 0) {
            int b0i = g * 33;
            #pragma unroll
            for (int a = 0; a < 8; a++) {
                int v = row0 + rg + 8 * a;
                if (v < NV) {
                    #pragma unroll
                    for (int q = 0; q < 4; q++) {
                        float sum = oa[a][q] + shP[b0i + a * 4 + q]
                                  + shP[2656 + b0i + a * 4 + q]
                                  + shP[5312 + b0i + a * 4 + q];
                        out[v * NC + j0 + q] = sum;
                    }
                }
            }
        }
    }
}

// ---------------- launch (fork/join: structure chain || GEMMs) ----------------
extern "C" void kernel_launch(void* const* d_in, const int* in_sizes, int n_in,
                              void* d_out, int out_size) {
    const float* x        = (const float*)d_in[0];
    const float* eattr    = (const float*)d_in[1];
    const int*   node_idx = (const int*)d_in[2];
    const int*   edge_idx = (const int*)d_in[3];
    const float* Wlin     = (const float*)d_in[4];
    const float* blin     = (const float*)d_in[5];
    const float* w1       = (const float*)d_in[6];
    const float* w2       = (const float*)d_in[7];
    const float* bs       = (const float*)d_in[8];
    const float* W0       = (const float*)d_in[9];
    const float* b0       = (const float*)d_in[10];
    const float* W1       = (const float*)d_in[11];
    const float* b1       = (const float*)d_in[12];
    const float* W2       = (const float*)d_in[13];
    float* out = (float*)d_out;

    cudaFuncSetAttribute(final_kernel, cudaFuncAttributeMaxDynamicSharedMemorySize,
                         FK2_FLOATS * 4);

    int gZ = (NNZ + 255) / 256;

    // transient fork stream + events (no device-mem delta; capture records DAG edges)
    cudaStream_t s2;
    cudaStreamCreateWithFlags(&s2, cudaStreamNonBlocking);
    cudaEvent_t evFork, evJoin;
    cudaEventCreateWithFlags(&evFork, cudaEventDisableTiming);
    cudaEventCreateWithFlags(&evJoin, cudaEventDisableTiming);

    // K1: zero + weight folding (root)
    init_all<<<ZBLK + FIN + 1, 256>>>(Wlin, blin, w1, w2, W0);
    cudaEventRecord(evFork, 0);

    // branch B (s2): lifted features — needs only init_all
    cudaStreamWaitEvent(s2, evFork, 0);
    gemms_kernel<<<NODE_BLOCKS + EDGE_BLOCKS, 128, 0, s2>>>(x, eattr);
    cudaEventRecord(evJoin, s2);

    // branch A (main): degree count + single-pass offsets
    count_deg<<<gZ, 256>>>(node_idx, edge_idx);
    scan_all<<<NBE + NBV, 1024>>>();

    // join: fill needs offsets (A) + a1/a2 (B)
    cudaStreamWaitEvent(0, evJoin, 0);
    fill_csr_s<<<gZ, 256>>>(node_idx, edge_idx, bs);

    // two sheaf-Laplacian passes
    edge_agg<<<(NE * 32 + 255) / 256, 256>>>(0);
    node_agg<<<(NV * 32 + 255) / 256, 256>>>(0, b0);
    edge_agg<<<(NE * 32 + 255) / 256, 256>>>(1);
    node_agg<<<(NV * 32 + 255) / 256, 256>>>(1, b0);

    // fused classifier head
    final_kernel<<<(NV + 63) / 64, 320, FK2_FLOATS * 4>>>(W1, b1, W2, out);

    cudaEventDestroy(evFork);
    cudaEventDestroy(evJoin);
    cudaStreamDestroy(s2);
}

// round 15
// speedup vs baseline: 1.0140x; 1.0140x over previous
#include <cuda_runtime.h>
#include <math.h>

#define NV 50000
#define NE 25000
#define NNZ 200000
#define FIN 128
#define NHID 256
#define ND 4
#define NH1 16
#define NC 40

// ---------------- device scratch (static; no allocation) ----------------
// Only ever referenced inside device code (GB300 ATS makes host-shadow
// dereference silently read zeros — never pass these as kernel args).
__device__ float g_u1[FIN * 4];
__device__ float g_u2[FIN * 4];
__device__ float g_WA[FIN * 64];
__device__ float g_bbG[64];
__device__ float g_ba1[4];
__device__ float g_ba2[4];

__device__ float4 g_a1[NV];
__device__ float4 g_a2[NE];

__device__ int g_cnt_e[NE], g_cnt_v[NV];
__device__ int g_off_e[NE], g_off_v[NV];
__device__ int g_cur_e[NE], g_cur_v[NV];
__device__ float g_inv_e[NE], g_inv_v[NV];

#define NBE 25
#define NBV 49
__device__ int g_aggE[NBE];    // published block aggregates (+1 ready-flag)
__device__ int g_aggV[NBV];

__device__ int g_vid_e[NNZ];   // node id per edge-CSR slot
__device__ int g_eid_v[NNZ];   // edge id per node-CSR slot
__device__ float4 g_se[NNZ];   // s in edge-CSR order
__device__ float4 g_sv[NNZ];   // s in node-CSR order

__device__ float g_P0[NV * 64];
__device__ float g_m[NE * 64];
__device__ float g_H1[NV * 64];
__device__ float g_T[NV * 64];

// ================= init: zero counters/flags + weight folding =================
#define ZBLK 196     // ceil(50000/256)
__global__ __launch_bounds__(256) void init_all(
    const float* __restrict__ Wlin, const float* __restrict__ blin,
    const float* __restrict__ w1, const float* __restrict__ w2,
    const float* __restrict__ W0) {
    int b = blockIdx.x, t = threadIdx.x;
    if (b < ZBLK) {
        int i = b * 256 + t;
        if (i < NE) { g_cnt_e[i] = 0; g_cur_e[i] = 0; }
        if (i < NV) { g_cnt_v[i] = 0; g_cur_v[i] = 0; }
        if (b == 0) {
            if (t < NBE) g_aggE[t] = 0;
            else if (t < NBE + NBV) g_aggV[t - NBE] = 0;
        }
        return;
    }
    int pb = b - ZBLK;                 // 0..128
    if (pb < FIN) {
        int f = pb;
        if (t < 64) {
            int d = t >> 4, c = t & 15;
            const float* wl = Wlin + f * (ND * NHID) + d * NHID;
            float acc = 0.0f;
            #pragma unroll 8
            for (int h = 0; h < NHID; h++) acc += wl[h] * W0[h * NH1 + c];
            g_WA[f * 64 + t] = acc;
        } else if (t < 68) {
            int d = t - 64;
            const float* wl = Wlin + f * (ND * NHID) + d * NHID;
            float acc = 0.0f;
            #pragma unroll 8
            for (int h = 0; h < NHID; h++) acc += wl[h] * w1[h * ND + d];
            g_u1[f * 4 + d] = acc;
        } else if (t < 72) {
            int d = t - 68;
            const float* wl = Wlin + f * (ND * NHID) + d * NHID;
            float acc = 0.0f;
            #pragma unroll 8
            for (int h = 0; h < NHID; h++) acc += wl[h] * w2[h * ND + d];
            g_u2[f * 4 + d] = acc;
        }
    } else {
        if (t < 64) {
            int d = t >> 4, c = t & 15;
            const float* bl = blin + d * NHID;
            float acc = 0.0f;
            #pragma unroll 8
            for (int h = 0; h < NHID; h++) acc += bl[h] * W0[h * NH1 + c];
            g_bbG[t] = acc;
        } else if (t < 68) {
            int d = t - 64;
            const float* bl = blin + d * NHID;
            float acc = 0.0f;
            for (int h = 0; h < NHID; h++) acc += bl[h] * w1[h * ND + d];
            g_ba1[d] = acc;
        } else if (t < 72) {
            int d = t - 68;
            const float* bl = blin + d * NHID;
            float acc = 0.0f;
            for (int h = 0; h < NHID; h++) acc += bl[h] * w2[h * ND + d];
            g_ba2[d] = acc;
        }
    }
}

// ================= structural kernels =================
__global__ void count_deg(const int* __restrict__ node_idx,
                          const int* __restrict__ edge_idx) {
    int i = blockIdx.x * blockDim.x + threadIdx.x;
    if (i >= NNZ) return;
    atomicAdd(&g_cnt_e[edge_idx[i]], 1);
    atomicAdd(&g_cnt_v[node_idx[i]], 1);
}

// single-pass scan with decoupled block aggregates (all 74 blocks co-resident)
__device__ __forceinline__ void scan_onepass_dev(const int* __restrict__ in, int n,
                                                 int* __restrict__ out,
                                                 float* __restrict__ inv,
                                                 int* __restrict__ agg,
                                                 int nblk, int blk) {
    __shared__ int wsum[32];
    __shared__ int s_pfx;
    int t = threadIdx.x;
    int i = blk * 1024 + t;
    int v = (i < n) ? in[i] : 0;
    if (i < n) inv[i] = v > 0 ? 1.0f / (float)v : 0.0f;
    int lane = t & 31, wid = t >> 5;
    int xv = v;
    #pragma unroll
    for (int o = 1; o < 32; o <<= 1) {
        int y = __shfl_up_sync(0xFFFFFFFFu, xv, o);
        if (lane >= o) xv += y;
    }
    if (lane == 31) wsum[wid] = xv;
    __syncthreads();
    if (wid == 0) {
        int s = wsum[lane];
        #pragma unroll
        for (int o = 1; o < 32; o <<= 1) {
            int y = __shfl_up_sync(0xFFFFFFFFu, s, o);
            if (lane >= o) s += y;
        }
        wsum[lane] = s;
        if (lane == 31) atomicExch(&agg[blk], s + 1);   // publish total (+1 flag)
        int sum = 0;
        for (int j = lane; j < blk; j += 32) {
            int a;
            do { a = atomicAdd(&agg[j], 0); } while (a == 0);
            sum += a - 1;
        }
        #pragma unroll
        for (int o = 16; o; o >>= 1) sum += __shfl_down_sync(0xFFFFFFFFu, sum, o);
        if (lane == 0) s_pfx = sum;
    }
    __syncthreads();
    int base = (wid > 0 ? wsum[wid - 1] : 0) + s_pfx;
    if (i < n) out[i] = base + xv - v;
}

__global__ void scan_all() {
    if (blockIdx.x < NBE)
        scan_onepass_dev(g_cnt_e, NE, g_off_e, g_inv_e, g_aggE, NBE, blockIdx.x);
    else
        scan_onepass_dev(g_cnt_v, NV, g_off_v, g_inv_v, g_aggV, NBV, blockIdx.x - NBE);
}

// ================= fused GEMMs: node (P0, a1) + edge (a2) =================
// node tile: 64 rows x 64 cols, 128 thr, 8x4 regs/thread -> 10.7 FMA per LDS.128
#define NODE_BLOCKS 782      // ceil(NV/64)
#define EDGE_BLOCKS 782      // ceil(NE*4/128)
__global__ __launch_bounds__(128) void gemms_kernel(const float* __restrict__ x,
                                                    const float* __restrict__ eattr) {
    if (blockIdx.x < NODE_BLOCKS) {
        __shared__ __align__(16) float shX[64][68];
        __shared__ __align__(16) float shWT[64][68];
        __shared__ __align__(16) float shUT[4][132];
        int t = threadIdx.x;
        int tx = t & 15, ty = t >> 4;          // tx 0..15, ty 0..7
        int row0 = blockIdx.x * 64;
        for (int i = t; i < 512; i += 128) {
            int d = i >> 7, f = i & 127;
            shUT[d][f] = g_u1[f * 4 + d];
        }
        float acc[8][4] = {};
        float accA0 = 0.0f, accA1 = 0.0f;
        int rA = t >> 2, dA = t & 3;           // rA 0..31; rows rA and rA+32
        for (int ch = 0; ch < 2; ch++) {
            int f0 = ch * 64;
            __syncthreads();
            for (int i = t; i < 4096; i += 128) {
                int r = i >> 6, f = i & 63;
                int v = row0 + r;
                shX[r][f] = (v < NV) ? x[v * FIN + f0 + f] : 0.0f;
            }
            for (int i = t; i < 4096; i += 128) {
                int f = i >> 6, c = i & 63;
                shWT[c][f] = g_WA[(f0 + f) * 64 + c];
            }
            __syncthreads();
            #pragma unroll
            for (int f4 = 0; f4 < 16; f4++) {
                float4 wv[4];
                #pragma unroll
                for (int q = 0; q < 4; q++)
                    wv[q] = *(const float4*)&shWT[tx + 16 * q][f4 * 4];
                #pragma unroll
                for (int a = 0; a < 8; a++) {
                    float4 xr = *(const float4*)&shX[ty + 8 * a][f4 * 4];
                    #pragma unroll
                    for (int q = 0; q < 4; q++)
                        acc[a][q] += xr.x * wv[q].x + xr.y * wv[q].y
                                   + xr.z * wv[q].z + xr.w * wv[q].w;
                }
            }
            #pragma unroll
            for (int f4 = 0; f4 < 16; f4++) {
                float4 uv = *(const float4*)&shUT[dA][f0 + f4 * 4];
                float4 x0 = *(const float4*)&shX[rA][f4 * 4];
                float4 x1 = *(const float4*)&shX[rA + 32][f4 * 4];
                accA0 += x0.x * uv.x + x0.y * uv.y + x0.z * uv.z + x0.w * uv.w;
                accA1 += x1.x * uv.x + x1.y * uv.y + x1.z * uv.z + x1.w * uv.w;
            }
        }
        #pragma unroll
        for (int a = 0; a < 8; a++) {
            int v = row0 + ty + 8 * a;
            if (v >= NV) continue;
            #pragma unroll
            for (int q = 0; q < 4; q++) {
                int c = tx + 16 * q;
                g_P0[v * 64 + c] = acc[a][q] + g_bbG[c];
            }
        }
        int vA0 = row0 + rA;
        int vA1 = row0 + rA + 32;
        if (vA0 < NV) ((float*)g_a1)[vA0 * 4 + dA] = accA0 + g_ba1[dA];
        if (vA1 < NV) ((float*)g_a1)[vA1 * 4 + dA] = accA1 + g_ba1[dA];
    } else {
        int id = (blockIdx.x - NODE_BLOCKS) * 128 + threadIdx.x;
        if (id >= NE * 4) return;
        int e = id >> 2, d = id & 3;
        const float* row = eattr + e * FIN;
        float acc = g_ba2[d];
        #pragma unroll 8
        for (int f = 0; f < FIN; f++) acc += row[f] * g_u2[f * 4 + d];
        ((float*)g_a2)[id] = acc;
    }
}

// ================= fill CSR + sheaf scalars, split into edge/node sides ======
__global__ void fill_e_kernel(const int* __restrict__ node_idx,
                              const int* __restrict__ edge_idx,
                              const float* __restrict__ bs) {
    int i = blockIdx.x * blockDim.x + threadIdx.x;
    if (i >= NNZ) return;
    int e = edge_idx[i];
    int v = node_idx[i];
    float4 A = g_a1[v];
    float4 B = g_a2[e];
    float4 r;
    r.x = tanhf(A.x + B.x + bs[0]);
    r.y = tanhf(A.y + B.y + bs[1]);
    r.z = tanhf(A.z + B.z + bs[2]);
    r.w = tanhf(A.w + B.w + bs[3]);
    int p = atomicAdd(&g_cur_e[e], 1);
    int pos = g_off_e[e] + p;
    g_vid_e[pos] = v;
    g_se[pos] = r;
}

__global__ void fill_v_kernel(const int* __restrict__ node_idx,
                              const int* __restrict__ edge_idx,
                              const float* __restrict__ bs) {
    int i = blockIdx.x * blockDim.x + threadIdx.x;
    if (i >= NNZ) return;
    int e = edge_idx[i];
    int v = node_idx[i];
    float4 A = g_a1[v];
    float4 B = g_a2[e];
    float4 r;
    r.x = tanhf(A.x + B.x + bs[0]);
    r.y = tanhf(A.y + B.y + bs[1]);
    r.z = tanhf(A.z + B.z + bs[2]);
    r.w = tanhf(A.w + B.w + bs[3]);
    int q = atomicAdd(&g_cur_v[v], 1);
    int pos2 = g_off_v[v] + q;
    g_eid_v[pos2] = e;
    g_sv[pos2] = r;
}

// ================= aggregation (warp/segment, payload CSR, float2) ===========
__device__ __forceinline__ float pick_s(const float4& s4, int dsel) {
    float lo = dsel < 1 ? s4.x : s4.y;
    float hi = dsel < 3 ? s4.z : s4.w;
    return dsel < 2 ? lo : hi;
}

__global__ void edge_agg(int src) {
    int w = (blockIdx.x * blockDim.x + threadIdx.x) >> 5;
    int lane = threadIdx.x & 31;
    if (w >= NE) return;
    const float* __restrict__ X = src ? g_H1 : g_P0;
    int beg = g_off_e[w], cnt = g_cnt_e[w];
    int dsel = lane >> 3;
    float2 acc = make_float2(0.0f, 0.0f);
    #pragma unroll 2
    for (int k = 0; k < cnt; k++) {
        int pos = beg + k;
        int v = g_vid_e[pos];
        float4 s4 = g_se[pos];
        float sd = pick_s(s4, dsel);
        float2 xr = *(const float2*)&X[v * 64 + lane * 2];
        acc.x += sd * xr.x;
        acc.y += sd * xr.y;
    }
    float inv = g_inv_e[w];
    ((float2*)g_m)[w * 32 + lane] = make_float2(acc.x * inv, acc.y * inv);
}

__global__ void node_agg(int layer, const float* __restrict__ b0) {
    int w = (blockIdx.x * blockDim.x + threadIdx.x) >> 5;
    int lane = threadIdx.x & 31;
    if (w >= NV) return;
    const float* __restrict__ Base = layer ? g_H1 : g_P0;
    float* __restrict__ Out = layer ? g_T : g_H1;
    int beg = g_off_v[w], cnt = g_cnt_v[w];
    int dsel = lane >> 3;
    float2 acc = make_float2(0.0f, 0.0f);
    #pragma unroll 2
    for (int k = 0; k < cnt; k++) {
        int pos = beg + k;
        int e = g_eid_v[pos];
        float4 s4 = g_sv[pos];
        float sd = pick_s(s4, dsel);
        float2 mr = ((const float2*)g_m)[e * 32 + lane];
        acc.x += sd * mr.x;
        acc.y += sd * mr.y;
    }
    float inv = g_inv_v[w];
    float2 base = ((const float2*)Base)[w * 32 + lane];
    float o0 = base.x - acc.x * inv;
    float o1 = base.y - acc.y * inv;
    if (layer == 0) {
        int c0 = lane * 2;
        o0 = fmaxf(o0 + b0[c0 & 15], 0.0f);
        o1 = fmaxf(o1 + b0[(c0 + 1) & 15], 0.0f);
    }
    ((float2*)Out)[w * 32 + lane] = make_float2(o0, o1);
}

// ================= final fused: out = relu(T @ blockdiag(W1) + b1) @ W2 ======
#define FK2_FLOATS (640 + 40 + 40 * 172 + 64 * 68 + 64 * 164)
__global__ __launch_bounds__(320, 2)
void final_kernel(const float* __restrict__ W1, const float* __restrict__ b1,
                  const float* __restrict__ W2, float* __restrict__ out) {
    extern __shared__ float sh[];
    float* shW1  = sh;                 // 640
    float* shb1  = sh + 640;           // 40
    float* shW2T = sh + 680;           // [j][k] stride 172
    float* shT   = sh + 7560;          // [r][c] stride 68
    float* shZ   = sh + 11912;         // [r][k] stride 164 (reused for partials)
    int t = threadIdx.x;
    for (int i = t; i < 640; i += 320) shW1[i] = W1[i];
    for (int i = t; i < 40; i += 320) shb1[i] = b1[i];
    for (int i = t; i < 6400; i += 320) {
        int k = i / 40, j = i % 40;
        shW2T[j * 172 + k] = W2[i];
    }
    int row0 = blockIdx.x * 64;
    for (int i = t; i < 4096; i += 320) {
        int r = i >> 6, c = i & 63;
        int v = row0 + r;
        shT[r * 68 + c] = (v < NV) ? g_T[v * 64 + c] : 0.0f;
    }
    __syncthreads();
    // Phase B: Z = relu(T @ blockdiag(W1) + b1)
    {
        int tx = t % 40, ty = t / 40;
        int d = tx / 10, cl = tx % 10;
        float zacc[8][4] = {};
        #pragma unroll
        for (int k = 0; k < 16; k++) {
            float tv[8], wv[4];
            #pragma unroll
            for (int a = 0; a < 8; a++) tv[a] = shT[(ty + 8 * a) * 68 + d * 16 + k];
            #pragma unroll
            for (int q = 0; q < 4; q++) wv[q] = shW1[k * 40 + cl + 10 * q];
            #pragma unroll
            for (int a = 0; a < 8; a++)
                #pragma unroll
                for (int q = 0; q < 4; q++) zacc[a][q] += tv[a] * wv[q];
        }
        #pragma unroll
        for (int a = 0; a < 8; a++)
            #pragma unroll
            for (int q = 0; q < 4; q++) {
                int j = cl + 10 * q;
                shZ[(ty + 8 * a) * 164 + d * 40 + j] = fmaxf(zacc[a][q] + shb1[j], 0.0f);
            }
    }
    __syncthreads();
    // Phase C: out = Z @ W2. 80 tiles (8 rows x 4 cols) x 4-way split-K.
    {
        int g = t % 80, kh = t / 80;        // kh 0..3
        int rg = g % 8, cg = g / 8;         // rg 0..7, cg 0..9
        int j0 = cg * 4;
        float oa[8][4] = {};
        int kbeg = kh * 40;
        #pragma unroll
        for (int k4 = 0; k4 < 10; k4++) {
            int k = kbeg + k4 * 4;
            float4 zv[8], wv[4];
            #pragma unroll
            for (int a = 0; a < 8; a++) zv[a] = *(const float4*)&shZ[(rg + 8 * a) * 164 + k];
            #pragma unroll
            for (int q = 0; q < 4; q++) wv[q] = *(const float4*)&shW2T[(j0 + q) * 172 + k];
            #pragma unroll
            for (int a = 0; a < 8; a++)
                #pragma unroll
                for (int q = 0; q < 4; q++)
                    oa[a][q] += zv[a].x * wv[q].x + zv[a].y * wv[q].y
                              + zv[a].z * wv[q].z + zv[a].w * wv[q].w;
        }
        __syncthreads();                    // all shZ reads done
        float* shP = shZ;                   // reuse as partial staging (3 x 80 x 33)
        if (kh) {
            int base = (kh - 1) * 2656 + g * 33;
            #pragma unroll
            for (int a = 0; a < 8; a++)
                #pragma unroll
                for (int q = 0; q < 4; q++) shP[base + a * 4 + q] = oa[a][q];
        }
        __syncthreads();
        if (kh == 0) {
            int b0i = g * 33;
            #pragma unroll
            for (int a = 0; a < 8; a++) {
                int v = row0 + rg + 8 * a;
                if (v < NV) {
                    #pragma unroll
                    for (int q = 0; q < 4; q++) {
                        float sum = oa[a][q] + shP[b0i + a * 4 + q]
                                  + shP[2656 + b0i + a * 4 + q]
                                  + shP[5312 + b0i + a * 4 + q];
                        out[v * NC + j0 + q] = sum;
                    }
                }
            }
        }
    }
}

// ---------------- launch (double fork/join) ----------------
extern "C" void kernel_launch(void* const* d_in, const int* in_sizes, int n_in,
                              void* d_out, int out_size) {
    const float* x        = (const float*)d_in[0];
    const float* eattr    = (const float*)d_in[1];
    const int*   node_idx = (const int*)d_in[2];
    const int*   edge_idx = (const int*)d_in[3];
    const float* Wlin     = (const float*)d_in[4];
    const float* blin     = (const float*)d_in[5];
    const float* w1       = (const float*)d_in[6];
    const float* w2       = (const float*)d_in[7];
    const float* bs       = (const float*)d_in[8];
    const float* W0       = (const float*)d_in[9];
    const float* b0       = (const float*)d_in[10];
    const float* W1       = (const float*)d_in[11];
    const float* b1       = (const float*)d_in[12];
    const float* W2       = (const float*)d_in[13];
    float* out = (float*)d_out;

    cudaFuncSetAttribute(final_kernel, cudaFuncAttributeMaxDynamicSharedMemorySize,
                         FK2_FLOATS * 4);

    int gZ = (NNZ + 255) / 256;

    // transient fork stream + events (no device-mem delta; capture records DAG edges)
    cudaStream_t s2;
    cudaStreamCreateWithFlags(&s2, cudaStreamNonBlocking);
    cudaEvent_t evFork, evJoin, evScan, evFv;
    cudaEventCreateWithFlags(&evFork, cudaEventDisableTiming);
    cudaEventCreateWithFlags(&evJoin, cudaEventDisableTiming);
    cudaEventCreateWithFlags(&evScan, cudaEventDisableTiming);
    cudaEventCreateWithFlags(&evFv, cudaEventDisableTiming);

    // K1: zero + weight folding (root)
    init_all<<<ZBLK + FIN + 1, 256>>>(Wlin, blin, w1, w2, W0);
    cudaEventRecord(evFork, 0);

    // branch B (s2): lifted features — needs only init_all
    cudaStreamWaitEvent(s2, evFork, 0);
    gemms_kernel<<<NODE_BLOCKS + EDGE_BLOCKS, 128, 0, s2>>>(x, eattr);
    cudaEventRecord(evJoin, s2);

    // branch A (main): degree count + single-pass offsets
    count_deg<<<gZ, 256>>>(node_idx, edge_idx);
    scan_all<<<NBE + NBV, 1024>>>();
    cudaEventRecord(evScan, 0);

    // main: edge-side fill (needs offsets + a1/a2) then eagg0 immediately
    cudaStreamWaitEvent(0, evJoin, 0);
    fill_e_kernel<<<gZ, 256>>>(node_idx, edge_idx, bs);

    // s2: node-side fill concurrently (needs gemms [in-order] + scan [event])
    cudaStreamWaitEvent(s2, evScan, 0);
    fill_v_kernel<<<gZ, 256, 0, s2>>>(node_idx, edge_idx, bs);
    cudaEventRecord(evFv, s2);

    edge_agg<<<(NE * 32 + 255) / 256, 256>>>(0);
    cudaStreamWaitEvent(0, evFv, 0);
    node_agg<<<(NV * 32 + 255) / 256, 256>>>(0, b0);
    edge_agg<<<(NE * 32 + 255) / 256, 256>>>(1);
    node_agg<<<(NV * 32 + 255) / 256, 256>>>(1, b0);

    // fused classifier head
    final_kernel<<<(NV + 63) / 64, 320, FK2_FLOATS * 4>>>(W1, b1, W2, out);

    cudaEventDestroy(evFork);
    cudaEventDestroy(evJoin);
    cudaEventDestroy(evScan);
    cudaEventDestroy(evFv);
    cudaStreamDestroy(s2);
}

// round 16
// speedup vs baseline: 1.0564x; 1.0419x over previous
#include <cuda_runtime.h>
#include <math.h>

#define NV 50000
#define NE 25000
#define NNZ 200000
#define FIN 128
#define NHID 256
#define ND 4
#define NH1 16
#define NC 40

// ---------------- device scratch (static; no allocation) ----------------
// Only ever referenced inside device code (GB300 ATS makes host-shadow
// dereference silently read zeros — never pass these as kernel args).
__device__ float g_u1[FIN * 4];
__device__ float g_u2[FIN * 4];
__device__ float g_WA[FIN * 64];
__device__ float g_bbG[64];
__device__ float g_ba1[4];
__device__ float g_ba2[4];

__device__ float4 g_a1[NV];
__device__ float4 g_a2[NE];

__device__ int g_cnt_e[NE], g_cnt_v[NV];
__device__ int g_off_e[NE], g_off_v[NV];
__device__ int g_cur_e[NE], g_cur_v[NV];
__device__ float g_inv_e[NE], g_inv_v[NV];

#define NBE 25
#define NBV 49
__device__ int g_aggE[NBE];    // published block aggregates (+1 ready-flag)
__device__ int g_aggV[NBV];

__device__ int g_vid_e[NNZ];   // node id per edge-CSR slot
__device__ int g_eid_v[NNZ];   // edge id per node-CSR slot
__device__ float4 g_se[NNZ];   // s in edge-CSR order
__device__ float4 g_sv[NNZ];   // s in node-CSR order

__device__ float g_P0[NV * 64];
__device__ float g_m[NE * 64];
__device__ float g_H1[NV * 64];
__device__ float g_T[NV * 64];

// ================= init: zero counters/flags + weight folding =================
#define ZBLK 196     // ceil(50000/256)
__global__ __launch_bounds__(256) void init_all(
    const float* __restrict__ Wlin, const float* __restrict__ blin,
    const float* __restrict__ w1, const float* __restrict__ w2,
    const float* __restrict__ W0) {
    int b = blockIdx.x, t = threadIdx.x;
    if (b < ZBLK) {
        int i = b * 256 + t;
        if (i < NE) { g_cnt_e[i] = 0; g_cur_e[i] = 0; }
        if (i < NV) { g_cnt_v[i] = 0; g_cur_v[i] = 0; }
        if (b == 0) {
            if (t < NBE) g_aggE[t] = 0;
            else if (t < NBE + NBV) g_aggV[t - NBE] = 0;
        }
        return;
    }
    int pb = b - ZBLK;                 // 0..128
    if (pb < FIN) {
        int f = pb;
        if (t < 64) {
            int d = t >> 4, c = t & 15;
            const float* wl = Wlin + f * (ND * NHID) + d * NHID;
            float acc = 0.0f;
            #pragma unroll 8
            for (int h = 0; h < NHID; h++) acc += wl[h] * W0[h * NH1 + c];
            g_WA[f * 64 + t] = acc;
        } else if (t < 68) {
            int d = t - 64;
            const float* wl = Wlin + f * (ND * NHID) + d * NHID;
            float acc = 0.0f;
            #pragma unroll 8
            for (int h = 0; h < NHID; h++) acc += wl[h] * w1[h * ND + d];
            g_u1[f * 4 + d] = acc;
        } else if (t < 72) {
            int d = t - 68;
            const float* wl = Wlin + f * (ND * NHID) + d * NHID;
            float acc = 0.0f;
            #pragma unroll 8
            for (int h = 0; h < NHID; h++) acc += wl[h] * w2[h * ND + d];
            g_u2[f * 4 + d] = acc;
        }
    } else {
        if (t < 64) {
            int d = t >> 4, c = t & 15;
            const float* bl = blin + d * NHID;
            float acc = 0.0f;
            #pragma unroll 8
            for (int h = 0; h < NHID; h++) acc += bl[h] * W0[h * NH1 + c];
            g_bbG[t] = acc;
        } else if (t < 68) {
            int d = t - 64;
            const float* bl = blin + d * NHID;
            float acc = 0.0f;
            for (int h = 0; h < NHID; h++) acc += bl[h] * w1[h * ND + d];
            g_ba1[d] = acc;
        } else if (t < 72) {
            int d = t - 68;
            const float* bl = blin + d * NHID;
            float acc = 0.0f;
            for (int h = 0; h < NHID; h++) acc += bl[h] * w2[h * ND + d];
            g_ba2[d] = acc;
        }
    }
}

// ================= structural kernels =================
__global__ void count_deg(const int* __restrict__ node_idx,
                          const int* __restrict__ edge_idx) {
    int i = blockIdx.x * blockDim.x + threadIdx.x;
    if (i >= NNZ) return;
    atomicAdd(&g_cnt_e[edge_idx[i]], 1);
    atomicAdd(&g_cnt_v[node_idx[i]], 1);
}

// single-pass scan with decoupled block aggregates (all 74 blocks co-resident)
__device__ __forceinline__ void scan_onepass_dev(const int* __restrict__ in, int n,
                                                 int* __restrict__ out,
                                                 float* __restrict__ inv,
                                                 int* __restrict__ agg,
                                                 int nblk, int blk) {
    __shared__ int wsum[32];
    __shared__ int s_pfx;
    int t = threadIdx.x;
    int i = blk * 1024 + t;
    int v = (i < n) ? in[i] : 0;
    if (i < n) inv[i] = v > 0 ? 1.0f / (float)v : 0.0f;
    int lane = t & 31, wid = t >> 5;
    int xv = v;
    #pragma unroll
    for (int o = 1; o < 32; o <<= 1) {
        int y = __shfl_up_sync(0xFFFFFFFFu, xv, o);
        if (lane >= o) xv += y;
    }
    if (lane == 31) wsum[wid] = xv;
    __syncthreads();
    if (wid == 0) {
        int s = wsum[lane];
        #pragma unroll
        for (int o = 1; o < 32; o <<= 1) {
            int y = __shfl_up_sync(0xFFFFFFFFu, s, o);
            if (lane >= o) s += y;
        }
        wsum[lane] = s;
        if (lane == 31) atomicExch(&agg[blk], s + 1);   // publish total (+1 flag)
        int sum = 0;
        for (int j = lane; j < blk; j += 32) {
            int a;
            do { a = atomicAdd(&agg[j], 0); } while (a == 0);
            sum += a - 1;
        }
        #pragma unroll
        for (int o = 16; o; o >>= 1) sum += __shfl_down_sync(0xFFFFFFFFu, sum, o);
        if (lane == 0) s_pfx = sum;
    }
    __syncthreads();
    int base = (wid > 0 ? wsum[wid - 1] : 0) + s_pfx;
    if (i < n) out[i] = base + xv - v;
}

__global__ void scan_all() {
    if (blockIdx.x < NBE)
        scan_onepass_dev(g_cnt_e, NE, g_off_e, g_inv_e, g_aggE, NBE, blockIdx.x);
    else
        scan_onepass_dev(g_cnt_v, NV, g_off_v, g_inv_v, g_aggV, NBV, blockIdx.x - NBE);
}

// ================= fused GEMMs: node (P0, a1) + edge (a2) =================
// node tile: 64 rows x 64 cols, 128 thr, 8x4 regs/thread -> 10.7 FMA per LDS.128
#define NODE_BLOCKS 782      // ceil(NV/64)
#define EDGE_BLOCKS 782      // ceil(NE*4/128)
__global__ __launch_bounds__(128) void gemms_kernel(const float* __restrict__ x,
                                                    const float* __restrict__ eattr) {
    if (blockIdx.x < NODE_BLOCKS) {
        __shared__ __align__(16) float shX[64][68];
        __shared__ __align__(16) float shWT[64][68];
        __shared__ __align__(16) float shUT[4][132];
        int t = threadIdx.x;
        int tx = t & 15, ty = t >> 4;          // tx 0..15, ty 0..7
        int row0 = blockIdx.x * 64;
        for (int i = t; i < 512; i += 128) {
            int d = i >> 7, f = i & 127;
            shUT[d][f] = g_u1[f * 4 + d];
        }
        float acc[8][4] = {};
        float accA0 = 0.0f, accA1 = 0.0f;
        int rA = t >> 2, dA = t & 3;           // rA 0..31; rows rA and rA+32
        for (int ch = 0; ch < 2; ch++) {
            int f0 = ch * 64;
            __syncthreads();
            for (int i = t; i < 4096; i += 128) {
                int r = i >> 6, f = i & 63;
                int v = row0 + r;
                shX[r][f] = (v < NV) ? x[v * FIN + f0 + f] : 0.0f;
            }
            for (int i = t; i < 4096; i += 128) {
                int f = i >> 6, c = i & 63;
                shWT[c][f] = g_WA[(f0 + f) * 64 + c];
            }
            __syncthreads();
            #pragma unroll
            for (int f4 = 0; f4 < 16; f4++) {
                float4 wv[4];
                #pragma unroll
                for (int q = 0; q < 4; q++)
                    wv[q] = *(const float4*)&shWT[tx + 16 * q][f4 * 4];
                #pragma unroll
                for (int a = 0; a < 8; a++) {
                    float4 xr = *(const float4*)&shX[ty + 8 * a][f4 * 4];
                    #pragma unroll
                    for (int q = 0; q < 4; q++)
                        acc[a][q] += xr.x * wv[q].x + xr.y * wv[q].y
                                   + xr.z * wv[q].z + xr.w * wv[q].w;
                }
            }
            #pragma unroll
            for (int f4 = 0; f4 < 16; f4++) {
                float4 uv = *(const float4*)&shUT[dA][f0 + f4 * 4];
                float4 x0 = *(const float4*)&shX[rA][f4 * 4];
                float4 x1 = *(const float4*)&shX[rA + 32][f4 * 4];
                accA0 += x0.x * uv.x + x0.y * uv.y + x0.z * uv.z + x0.w * uv.w;
                accA1 += x1.x * uv.x + x1.y * uv.y + x1.z * uv.z + x1.w * uv.w;
            }
        }
        #pragma unroll
        for (int a = 0; a < 8; a++) {
            int v = row0 + ty + 8 * a;
            if (v >= NV) continue;
            #pragma unroll
            for (int q = 0; q < 4; q++) {
                int c = tx + 16 * q;
                g_P0[v * 64 + c] = acc[a][q] + g_bbG[c];
            }
        }
        int vA0 = row0 + rA;
        int vA1 = row0 + rA + 32;
        if (vA0 < NV) ((float*)g_a1)[vA0 * 4 + dA] = accA0 + g_ba1[dA];
        if (vA1 < NV) ((float*)g_a1)[vA1 * 4 + dA] = accA1 + g_ba1[dA];
    } else {
        int id = (blockIdx.x - NODE_BLOCKS) * 128 + threadIdx.x;
        if (id >= NE * 4) return;
        int e = id >> 2, d = id & 3;
        const float* row = eattr + e * FIN;
        float acc = g_ba2[d];
        #pragma unroll 8
        for (int f = 0; f < FIN; f++) acc += row[f] * g_u2[f * 4 + d];
        ((float*)g_a2)[id] = acc;
    }
}

// ================= fill CSR + sheaf scalars, split into edge/node sides ======
__global__ void fill_e_kernel(const int* __restrict__ node_idx,
                              const int* __restrict__ edge_idx,
                              const float* __restrict__ bs) {
    int i = blockIdx.x * blockDim.x + threadIdx.x;
    if (i >= NNZ) return;
    int e = edge_idx[i];
    int v = node_idx[i];
    float4 A = g_a1[v];
    float4 B = g_a2[e];
    float4 r;
    r.x = tanhf(A.x + B.x + bs[0]);
    r.y = tanhf(A.y + B.y + bs[1]);
    r.z = tanhf(A.z + B.z + bs[2]);
    r.w = tanhf(A.w + B.w + bs[3]);
    int p = atomicAdd(&g_cur_e[e], 1);
    int pos = g_off_e[e] + p;
    g_vid_e[pos] = v;
    g_se[pos] = r;
}

__global__ void fill_v_kernel(const int* __restrict__ node_idx,
                              const int* __restrict__ edge_idx,
                              const float* __restrict__ bs) {
    int i = blockIdx.x * blockDim.x + threadIdx.x;
    if (i >= NNZ) return;
    int e = edge_idx[i];
    int v = node_idx[i];
    float4 A = g_a1[v];
    float4 B = g_a2[e];
    float4 r;
    r.x = tanhf(A.x + B.x + bs[0]);
    r.y = tanhf(A.y + B.y + bs[1]);
    r.z = tanhf(A.z + B.z + bs[2]);
    r.w = tanhf(A.w + B.w + bs[3]);
    int q = atomicAdd(&g_cur_v[v], 1);
    int pos2 = g_off_v[v] + q;
    g_eid_v[pos2] = e;
    g_sv[pos2] = r;
}

// ================= aggregation: HALF-WARP per segment, float4 channels =======
// lane16 = lane & 15 owns channels {4*lane16 .. 4*lane16+3}, all in stalk
// d = lane16 >> 2. Two independent segments per warp -> 2x MLP.
__device__ __forceinline__ float pick_s(const float4& s4, int dsel) {
    float lo = dsel < 1 ? s4.x : s4.y;
    float hi = dsel < 3 ? s4.z : s4.w;
    return dsel < 2 ? lo : hi;
}

__global__ void edge_agg(int src) {
    int hw = (blockIdx.x * blockDim.x + threadIdx.x) >> 4;   // half-warp id
    int lane16 = threadIdx.x & 15;
    if (hw >= NE) return;
    const float* __restrict__ X = src ? g_H1 : g_P0;
    int beg = g_off_e[hw], cnt = g_cnt_e[hw];
    int dsel = lane16 >> 2;
    float4 acc = make_float4(0.0f, 0.0f, 0.0f, 0.0f);
    #pragma unroll 2
    for (int k = 0; k < cnt; k++) {
        int pos = beg + k;
        int v = g_vid_e[pos];
        float4 s4 = g_se[pos];
        float sd = pick_s(s4, dsel);
        float4 xr = *(const float4*)&X[v * 64 + lane16 * 4];
        acc.x += sd * xr.x;
        acc.y += sd * xr.y;
        acc.z += sd * xr.z;
        acc.w += sd * xr.w;
    }
    float inv = g_inv_e[hw];
    ((float4*)g_m)[hw * 16 + lane16] =
        make_float4(acc.x * inv, acc.y * inv, acc.z * inv, acc.w * inv);
}

__global__ void node_agg(int layer, const float* __restrict__ b0) {
    int hw = (blockIdx.x * blockDim.x + threadIdx.x) >> 4;
    int lane16 = threadIdx.x & 15;
    if (hw >= NV) return;
    const float* __restrict__ Base = layer ? g_H1 : g_P0;
    float* __restrict__ Out = layer ? g_T : g_H1;
    int beg = g_off_v[hw], cnt = g_cnt_v[hw];
    int dsel = lane16 >> 2;
    float4 acc = make_float4(0.0f, 0.0f, 0.0f, 0.0f);
    #pragma unroll 2
    for (int k = 0; k < cnt; k++) {
        int pos = beg + k;
        int e = g_eid_v[pos];
        float4 s4 = g_sv[pos];
        float sd = pick_s(s4, dsel);
        float4 mr = ((const float4*)g_m)[e * 16 + lane16];
        acc.x += sd * mr.x;
        acc.y += sd * mr.y;
        acc.z += sd * mr.z;
        acc.w += sd * mr.w;
    }
    float inv = g_inv_v[hw];
    float4 base = ((const float4*)Base)[hw * 16 + lane16];
    float o0 = base.x - acc.x * inv;
    float o1 = base.y - acc.y * inv;
    float o2 = base.z - acc.z * inv;
    float o3 = base.w - acc.w * inv;
    if (layer == 0) {
        int c0 = lane16 * 4;           // channels c0..c0+3; bias index (c & 15)
        o0 = fmaxf(o0 + b0[c0 & 15], 0.0f);
        o1 = fmaxf(o1 + b0[(c0 + 1) & 15], 0.0f);
        o2 = fmaxf(o2 + b0[(c0 + 2) & 15], 0.0f);
        o3 = fmaxf(o3 + b0[(c0 + 3) & 15], 0.0f);
    }
    ((float4*)Out)[hw * 16 + lane16] = make_float4(o0, o1, o2, o3);
}

// ================= final fused: out = relu(T @ blockdiag(W1) + b1) @ W2 ======
#define FK2_FLOATS (640 + 40 + 40 * 172 + 64 * 68 + 64 * 164)
__global__ __launch_bounds__(320, 2)
void final_kernel(const float* __restrict__ W1, const float* __restrict__ b1,
                  const float* __restrict__ W2, float* __restrict__ out) {
    extern __shared__ float sh[];
    float* shW1  = sh;                 // 640
    float* shb1  = sh + 640;           // 40
    float* shW2T = sh + 680;           // [j][k] stride 172
    float* shT   = sh + 7560;          // [r][c] stride 68
    float* shZ   = sh + 11912;         // [r][k] stride 164 (reused for partials)
    int t = threadIdx.x;
    for (int i = t; i < 640; i += 320) shW1[i] = W1[i];
    for (int i = t; i < 40; i += 320) shb1[i] = b1[i];
    for (int i = t; i < 6400; i += 320) {
        int k = i / 40, j = i % 40;
        shW2T[j * 172 + k] = W2[i];
    }
    int row0 = blockIdx.x * 64;
    for (int i = t; i < 4096; i += 320) {
        int r = i >> 6, c = i & 63;
        int v = row0 + r;
        shT[r * 68 + c] = (v < NV) ? g_T[v * 64 + c] : 0.0f;
    }
    __syncthreads();
    // Phase B: Z = relu(T @ blockdiag(W1) + b1)
    {
        int tx = t % 40, ty = t / 40;
        int d = tx / 10, cl = tx % 10;
        float zacc[8][4] = {};
        #pragma unroll
        for (int k = 0; k < 16; k++) {
            float tv[8], wv[4];
            #pragma unroll
            for (int a = 0; a < 8; a++) tv[a] = shT[(ty + 8 * a) * 68 + d * 16 + k];
            #pragma unroll
            for (int q = 0; q < 4; q++) wv[q] = shW1[k * 40 + cl + 10 * q];
            #pragma unroll
            for (int a = 0; a < 8; a++)
                #pragma unroll
                for (int q = 0; q < 4; q++) zacc[a][q] += tv[a] * wv[q];
        }
        #pragma unroll
        for (int a = 0; a < 8; a++)
            #pragma unroll
            for (int q = 0; q < 4; q++) {
                int j = cl + 10 * q;
                shZ[(ty + 8 * a) * 164 + d * 40 + j] = fmaxf(zacc[a][q] + shb1[j], 0.0f);
            }
    }
    __syncthreads();
    // Phase C: out = Z @ W2. 80 tiles (8 rows x 4 cols) x 4-way split-K.
    {
        int g = t % 80, kh = t / 80;        // kh 0..3
        int rg = g % 8, cg = g / 8;         // rg 0..7, cg 0..9
        int j0 = cg * 4;
        float oa[8][4] = {};
        int kbeg = kh * 40;
        #pragma unroll
        for (int k4 = 0; k4 < 10; k4++) {
            int k = kbeg + k4 * 4;
            float4 zv[8], wv[4];
            #pragma unroll
            for (int a = 0; a < 8; a++) zv[a] = *(const float4*)&shZ[(rg + 8 * a) * 164 + k];
            #pragma unroll
            for (int q = 0; q < 4; q++) wv[q] = *(const float4*)&shW2T[(j0 + q) * 172 + k];
            #pragma unroll
            for (int a = 0; a < 8; a++)
                #pragma unroll
                for (int q = 0; q < 4; q++)
                    oa[a][q] += zv[a].x * wv[q].x + zv[a].y * wv[q].y
                              + zv[a].z * wv[q].z + zv[a].w * wv[q].w;
        }
        __syncthreads();                    // all shZ reads done
        float* shP = shZ;                   // reuse as partial staging (3 x 80 x 33)
        if (kh) {
            int base = (kh - 1) * 2656 + g * 33;
            #pragma unroll
            for (int a = 0; a < 8; a++)
                #pragma unroll
                for (int q = 0; q < 4; q++) shP[base + a * 4 + q] = oa[a][q];
        }
        __syncthreads();
        if (kh == 0) {
            int b0i = g * 33;
            #pragma unroll
            for (int a = 0; a < 8; a++) {
                int v = row0 + rg + 8 * a;
                if (v < NV) {
                    #pragma unroll
                    for (int q = 0; q < 4; q++) {
                        float sum = oa[a][q] + shP[b0i + a * 4 + q]
                                  + shP[2656 + b0i + a * 4 + q]
                                  + shP[5312 + b0i + a * 4 + q];
                        out[v * NC + j0 + q] = sum;
                    }
                }
            }
        }
    }
}

// ---------------- launch (double fork/join) ----------------
extern "C" void kernel_launch(void* const* d_in, const int* in_sizes, int n_in,
                              void* d_out, int out_size) {
    const float* x        = (const float*)d_in[0];
    const float* eattr    = (const float*)d_in[1];
    const int*   node_idx = (const int*)d_in[2];
    const int*   edge_idx = (const int*)d_in[3];
    const float* Wlin     = (const float*)d_in[4];
    const float* blin     = (const float*)d_in[5];
    const float* w1       = (const float*)d_in[6];
    const float* w2       = (const float*)d_in[7];
    const float* bs       = (const float*)d_in[8];
    const float* W0       = (const float*)d_in[9];
    const float* b0       = (const float*)d_in[10];
    const float* W1       = (const float*)d_in[11];
    const float* b1       = (const float*)d_in[12];
    const float* W2       = (const float*)d_in[13];
    float* out = (float*)d_out;

    cudaFuncSetAttribute(final_kernel, cudaFuncAttributeMaxDynamicSharedMemorySize,
                         FK2_FLOATS * 4);

    int gZ = (NNZ + 255) / 256;

    // transient fork stream + events (no device-mem delta; capture records DAG edges)
    cudaStream_t s2;
    cudaStreamCreateWithFlags(&s2, cudaStreamNonBlocking);
    cudaEvent_t evFork, evJoin, evScan, evFv;
    cudaEventCreateWithFlags(&evFork, cudaEventDisableTiming);
    cudaEventCreateWithFlags(&evJoin, cudaEventDisableTiming);
    cudaEventCreateWithFlags(&evScan, cudaEventDisableTiming);
    cudaEventCreateWithFlags(&evFv, cudaEventDisableTiming);

    // K1: zero + weight folding (root)
    init_all<<<ZBLK + FIN + 1, 256>>>(Wlin, blin, w1, w2, W0);
    cudaEventRecord(evFork, 0);

    // branch B (s2): lifted features — needs only init_all
    cudaStreamWaitEvent(s2, evFork, 0);
    gemms_kernel<<<NODE_BLOCKS + EDGE_BLOCKS, 128, 0, s2>>>(x, eattr);
    cudaEventRecord(evJoin, s2);

    // branch A (main): degree count + single-pass offsets
    count_deg<<<gZ, 256>>>(node_idx, edge_idx);
    scan_all<<<NBE + NBV, 1024>>>();
    cudaEventRecord(evScan, 0);

    // main: edge-side fill (needs offsets + a1/a2) then eagg0 immediately
    cudaStreamWaitEvent(0, evJoin, 0);
    fill_e_kernel<<<gZ, 256>>>(node_idx, edge_idx, bs);

    // s2: node-side fill concurrently (needs gemms [in-order] + scan [event])
    cudaStreamWaitEvent(s2, evScan, 0);
    fill_v_kernel<<<gZ, 256, 0, s2>>>(node_idx, edge_idx, bs);
    cudaEventRecord(evFv, s2);

    edge_agg<<<(NE * 16 + 255) / 256, 256>>>(0);
    cudaStreamWaitEvent(0, evFv, 0);
    node_agg<<<(NV * 16 + 255) / 256, 256>>>(0, b0);
    edge_agg<<<(NE * 16 + 255) / 256, 256>>>(1);
    node_agg<<<(NV * 16 + 255) / 256, 256>>>(1, b0);

    // fused classifier head
    final_kernel<<<(NV + 63) / 64, 320, FK2_FLOATS * 4>>>(W1, b1, W2, out);

    cudaEventDestroy(evFork);
    cudaEventDestroy(evJoin);
    cudaEventDestroy(evScan);
    cudaEventDestroy(evFv);
    cudaStreamDestroy(s2);
}